// round 2
// baseline (speedup 1.0000x reference)
#include <cuda_runtime.h>
#include <math.h>

#define BB 256
#define FF 256
#define DD 512
#define NJ3v 51
#define INDIM 34
#define G4 2048       // 4*D gate rows
#define KTOT 1024     // packed K (512 + 512)
#define MCW 563       // D + NJ3

// ---------------- static device scratch (no runtime allocation) ----------------
__device__ float g_Xp[(size_t)BB * FF * G4];   // 512 MB: per-(t,b) gate base
__device__ float g_WA[(size_t)G4 * KTOT];      // [Whh0 | Wcomb]
__device__ float g_WB[(size_t)G4 * KTOT];      // [Wih1 | Whh1]
__device__ float g_Wx[INDIM * G4];             // embed_W @ Wih0x^T
__device__ float g_bx[G4];
__device__ float g_cpred[G4];                  // dec_b @ Wih0pred^T
__device__ float g_bias1[G4];
__device__ float g_p0c[BB * G4];               // pred0 @ Wih0pred^T
__device__ float g_h0[2][BB * DD];
__device__ float g_h1[2][BB * DD];
__device__ float g_c0[BB * DD];
__device__ float g_c1[BB * DD];
__device__ float g_z1[BB * DD];
__device__ float g_z2[BB * 1024];

// ---------------- helpers ----------------
__device__ __forceinline__ float sigf(float x) { return 1.0f / (1.0f + expf(-x)); }

__device__ __forceinline__ unsigned long long pack2(float x, float y) {
    unsigned long long r;
    asm("mov.b64 %0, {%1, %2};" : "=l"(r) : "f"(x), "f"(y));
    return r;
}
__device__ __forceinline__ void ffma2(unsigned long long& a, unsigned long long b, unsigned long long c) {
    asm("fma.rn.f32x2 %0, %1, %2, %0;" : "+l"(a) : "l"(b), "l"(c));
}
__device__ __forceinline__ float lo2(unsigned long long v) { return __uint_as_float((unsigned)v); }
__device__ __forceinline__ float hi2(unsigned long long v) { return __uint_as_float((unsigned)(v >> 32)); }

// ---------------- one-time precompute kernels ----------------

// Wx[i][j] = sum_k embed_W[i,k] * Wih0[j,k]   (k < 512)
__global__ void wx_kernel(const float* __restrict__ embed_W, const float* __restrict__ Wih0) {
    int idx = blockIdx.x * 256 + threadIdx.x;
    if (idx >= INDIM * G4) return;
    int i = idx / G4, j = idx % G4;
    float s = 0.f;
    const float* wr = Wih0 + (size_t)j * MCW;
    const float* er = embed_W + (size_t)i * DD;
    for (int k = 0; k < DD; k++) s += er[k] * wr[k];
    g_Wx[idx] = s;
}

// bx[j] = embed_b @ Wih0x^T + bih0 + bhh0 ; cpred[j] = dec_b @ Wih0pred^T ; bias1
__global__ void bias_kernel(const float* __restrict__ embed_b, const float* __restrict__ Wih0,
                            const float* __restrict__ bih0, const float* __restrict__ bhh0,
                            const float* __restrict__ bih1, const float* __restrict__ bhh1,
                            const float* __restrict__ dec_b) {
    int j = blockIdx.x * 256 + threadIdx.x;
    if (j >= G4) return;
    const float* wr = Wih0 + (size_t)j * MCW;
    float s = bih0[j] + bhh0[j];
    for (int k = 0; k < DD; k++) s += embed_b[k] * wr[k];
    g_bx[j] = s;
    float cp = 0.f;
    for (int m = 0; m < NJ3v; m++) cp += dec_b[m] * wr[DD + m];
    g_cpred[j] = cp;
    g_bias1[j] = bih1[j] + bhh1[j];
}

// p0c[b][j] = pred0[b] @ Wih0pred^T   (pred0 = init[b,0,:51])
__global__ void p0c_kernel(const float* __restrict__ initp, const float* __restrict__ Wih0) {
    int idx = blockIdx.x * 256 + threadIdx.x;  // BB*G4
    int b = idx >> 11, j = idx & (G4 - 1);
    const float* wr = Wih0 + (size_t)j * MCW + DD;
    const float* p0 = initp + (size_t)b * 85;
    float s = 0.f;
    for (int m = 0; m < NJ3v; m++) s += p0[m] * wr[m];
    g_p0c[idx] = s;
}

// WA = [Whh0 | Wcomb],  Wcomb[j][k] = sum_m Wih0[j,512+m] * dec_W[k,m]
__global__ void packA_kernel(const float* __restrict__ Whh0, const float* __restrict__ Wih0,
                             const float* __restrict__ dec_W) {
    int idx = blockIdx.x * 256 + threadIdx.x;  // G4*KTOT
    int j = idx >> 10, k = idx & (KTOT - 1);
    float v;
    if (k < DD) {
        v = Whh0[(size_t)j * DD + k];
    } else {
        int kk = k - DD;
        const float* wr = Wih0 + (size_t)j * MCW + DD;
        const float* dr = dec_W + (size_t)kk * NJ3v;
        float s = 0.f;
        for (int m = 0; m < NJ3v; m++) s += wr[m] * dr[m];
        v = s;
    }
    g_WA[idx] = v;
}

__global__ void packB_kernel(const float* __restrict__ Wih1, const float* __restrict__ Whh1) {
    int idx = blockIdx.x * 256 + threadIdx.x;
    int j = idx >> 10, k = idx & (KTOT - 1);
    g_WB[idx] = (k < DD) ? Wih1[(size_t)j * DD + k] : Whh1[(size_t)j * DD + (k - DD)];
}

// init-net MLP
__global__ void init1_kernel(const float* __restrict__ initp, const float* __restrict__ W,
                             const float* __restrict__ b) {
    int idx = blockIdx.x * 256 + threadIdx.x;  // BB*DD
    int bb = idx >> 9, j = idx & (DD - 1);
    float s = b[j];
    const float* ir = initp + (size_t)bb * 85;
    for (int i = 0; i < 85; i++) s += ir[i] * W[(size_t)i * DD + j];
    g_z1[idx] = fmaxf(s, 0.f);
}
__global__ void init2_kernel(const float* __restrict__ W, const float* __restrict__ b) {
    int idx = blockIdx.x * 256 + threadIdx.x;  // BB*1024
    int bb = idx >> 10, j = idx & 1023;
    float s = b[j];
    const float* zr = g_z1 + (size_t)bb * DD;
    for (int k = 0; k < DD; k++) s += zr[k] * W[(size_t)k * 1024 + j];
    g_z2[idx] = fmaxf(s, 0.f);
}
__global__ void init3_kernel(const float* __restrict__ W, const float* __restrict__ b) {
    int idx = blockIdx.x * 256 + threadIdx.x;  // BB*G4
    int bb = idx >> 11, j = idx & (G4 - 1);
    float s = b[j];
    const float* zr = g_z2 + (size_t)bb * 1024;
    for (int k = 0; k < 1024; k++) s += zr[k] * W[(size_t)k * G4 + j];
    // z.reshape(b,2,L,D): [b][0][l][d] -> h layer l ; [b][1][l][d] -> c layer l
    if (j < DD)            g_h0[0][(size_t)bb * DD + j] = s;
    else if (j < 2 * DD)   g_h1[0][(size_t)bb * DD + (j - DD)] = s;
    else if (j < 3 * DD)   g_c0[(size_t)bb * DD + (j - 2 * DD)] = s;
    else                   g_c1[(size_t)bb * DD + (j - 3 * DD)] = s;
}

// Xp[row=t*B+b][j] = x[b,t,:] @ Wx[:,j] + bx[j] + (t==0 ? p0c[b][j] : cpred[j])
__global__ void xp_kernel(const float* __restrict__ x) {
    __shared__ float sX[32][INDIM];
    int j = blockIdx.x * 256 + threadIdx.x;  // grid.x = 8
    int r0 = blockIdx.y * 32;
    for (int idx = threadIdx.x; idx < 32 * INDIM; idx += 256) {
        int r = idx / INDIM, i = idx % INDIM;
        int row = r0 + r;
        int tt = row >> 8, b = row & 255;
        sX[r][i] = x[((size_t)b * FF + tt) * INDIM + i];
    }
    __syncthreads();
    float wcol[INDIM];
#pragma unroll
    for (int i = 0; i < INDIM; i++) wcol[i] = g_Wx[i * G4 + j];
    float bxj = g_bx[j], cpj = g_cpred[j];
    for (int r = 0; r < 32; r++) {
        int row = r0 + r;
        int tt = row >> 8, b = row & 255;
        float acc = bxj + ((tt == 0) ? g_p0c[(size_t)b * G4 + j] : cpj);
#pragma unroll
        for (int i = 0; i < INDIM; i++) acc += sX[r][i] * wcol[i];
        g_Xp[(size_t)row * G4 + j] = acc;
    }
}

// ---------------- the recurrent step kernel (GEMM + fused LSTM cell) ----------------
// gates[b][g*512+d] = base + sum_{k<1024} in[b][k] * W[g*512+d][k],   in = concat(in0,in1)
// then cell update: c' = sig(f)*c + sig(i)*tanh(g); h = sig(o)*tanh(c')
__global__ __launch_bounds__(256) void lstm_step(
    const float* __restrict__ W, const float* __restrict__ in0, const float* __restrict__ in1,
    const float* __restrict__ base, int bstride,
    float* __restrict__ cst, float* __restrict__ hout, float* __restrict__ mc, int t) {
    __shared__ float sIn[32][34];    // [k][b], padded to 34 (8B-aligned float2 reads)
    __shared__ float sW[128][33];    // [4g*32d][k], padded -> conflict-free

    const int tid = threadIdx.x;
    const int tx = tid & 31;   // d_local
    const int bg = tid >> 5;   // batch group 0..7 (4 rows each)
    const int d0 = blockIdx.x * 32;
    const int b0 = blockIdx.y * 32;

    unsigned long long acc[4][2];
#pragma unroll
    for (int g = 0; g < 4; g++) {
        acc[g][0] = 0ull; acc[g][1] = 0ull;
    }

    for (int kt = 0; kt < KTOT; kt += 32) {
        // stage input tile (transposed): sIn[k][b]
#pragma unroll
        for (int l = 0; l < 4; l++) {
            int idx = tid + l * 256;           // 0..1023
            int bl = idx >> 5, kl = idx & 31;
            int k = kt + kl;
            float v = (k < DD) ? in0[(size_t)(b0 + bl) * DD + k]
                               : in1[(size_t)(b0 + bl) * DD + (k - DD)];
            sIn[kl][bl] = v;
        }
        // stage weight tile: 128 gate-rows x 32 k
#pragma unroll
        for (int l = 0; l < 16; l++) {
            int idx = tid + l * 256;           // 0..4095
            int row = idx >> 5, col = idx & 31;
            int g = row >> 5, r = row & 31;
            sW[row][col] = W[(size_t)(g * DD + d0 + r) * KTOT + kt + col];
        }
        __syncthreads();
#pragma unroll
        for (int k = 0; k < 32; k++) {
            unsigned long long i0 = *(const unsigned long long*)&sIn[k][bg * 4];
            unsigned long long i1 = *(const unsigned long long*)&sIn[k][bg * 4 + 2];
#pragma unroll
            for (int g = 0; g < 4; g++) {
                float w = sW[g * 32 + tx][k];
                unsigned long long w2 = pack2(w, w);
                ffma2(acc[g][0], i0, w2);
                ffma2(acc[g][1], i1, w2);
            }
        }
        __syncthreads();
    }

    // epilogue: LSTM cell for 4 batch rows
    const int d = d0 + tx;
#pragma unroll
    for (int p = 0; p < 4; p++) {
        int b = b0 + bg * 4 + p;
        int pair = p >> 1, lane = p & 1;
        float gi = lane ? hi2(acc[0][pair]) : lo2(acc[0][pair]);
        float gf = lane ? hi2(acc[1][pair]) : lo2(acc[1][pair]);
        float gg = lane ? hi2(acc[2][pair]) : lo2(acc[2][pair]);
        float go = lane ? hi2(acc[3][pair]) : lo2(acc[3][pair]);
        const float* brow = base + (size_t)b * bstride;
        gi += brow[0 * DD + d];
        gf += brow[1 * DD + d];
        gg += brow[2 * DD + d];
        go += brow[3 * DD + d];
        size_t idx = (size_t)b * DD + d;
        float cn = sigf(gf) * cst[idx] + sigf(gi) * tanhf(gg);
        cst[idx] = cn;
        float h = sigf(go) * tanhf(cn);
        hout[idx] = h;
        if (mc) mc[((size_t)b * FF + t) * MCW + d] = h;
    }
}

// ---------------- final decode: preds from stored h1 context ----------------
__global__ __launch_bounds__(256) void dec_kernel(const float* __restrict__ dec_W,
                                                  const float* __restrict__ dec_b,
                                                  float* __restrict__ out_kp, float* __restrict__ mc) {
    __shared__ float sh[4][DD];
    size_t row0 = (size_t)blockIdx.x * 4;
    for (int idx = threadIdx.x; idx < 4 * DD; idx += 256)
        sh[idx >> 9][idx & (DD - 1)] = mc[(row0 + (idx >> 9)) * MCW + (idx & (DD - 1))];
    __syncthreads();
    int r = threadIdx.x >> 6, c = threadIdx.x & 63;
    if (c < NJ3v) {
        float s = dec_b[c];
        for (int k = 0; k < DD; k++) s += sh[r][k] * dec_W[(size_t)k * NJ3v + c];
        size_t row = row0 + r;
        out_kp[row * NJ3v + c] = s;
        mc[row * MCW + DD + c] = s;
    }
}

// ---------------- launch ----------------
extern "C" void kernel_launch(void* const* d_in, const int* in_sizes, int n_in,
                              void* d_out, int out_size) {
    const float* x       = (const float*)d_in[0];
    const float* initp   = (const float*)d_in[1];
    const float* embed_W = (const float*)d_in[2];
    const float* embed_b = (const float*)d_in[3];
    const float* ni_W1   = (const float*)d_in[4];
    const float* ni_b1   = (const float*)d_in[5];
    const float* ni_W2   = (const float*)d_in[6];
    const float* ni_b2   = (const float*)d_in[7];
    const float* ni_W3   = (const float*)d_in[8];
    const float* ni_b3   = (const float*)d_in[9];
    const float* Wih0    = (const float*)d_in[10];
    const float* Whh0    = (const float*)d_in[11];
    const float* bih0    = (const float*)d_in[12];
    const float* bhh0    = (const float*)d_in[13];
    const float* Wih1    = (const float*)d_in[14];
    const float* Whh1    = (const float*)d_in[15];
    const float* bih1    = (const float*)d_in[16];
    const float* bhh1    = (const float*)d_in[17];
    const float* dec_W   = (const float*)d_in[18];
    const float* dec_b   = (const float*)d_in[19];

    float* out = (float*)d_out;
    float* kp = out;                                  // (B,F,17,3)
    float* mc = out + (size_t)BB * FF * NJ3v;         // (B,F,563)

    float *Xp, *WA, *WB, *h0, *h1, *c0, *c1, *bias1v;
    cudaGetSymbolAddress((void**)&Xp, g_Xp);
    cudaGetSymbolAddress((void**)&WA, g_WA);
    cudaGetSymbolAddress((void**)&WB, g_WB);
    cudaGetSymbolAddress((void**)&h0, g_h0);
    cudaGetSymbolAddress((void**)&h1, g_h1);
    cudaGetSymbolAddress((void**)&c0, g_c0);
    cudaGetSymbolAddress((void**)&c1, g_c1);
    cudaGetSymbolAddress((void**)&bias1v, g_bias1);

    // one-time precompute (parallel)
    wx_kernel<<<272, 256>>>(embed_W, Wih0);
    bias_kernel<<<8, 256>>>(embed_b, Wih0, bih0, bhh0, bih1, bhh1, dec_b);
    p0c_kernel<<<2048, 256>>>(initp, Wih0);
    packA_kernel<<<8192, 256>>>(Whh0, Wih0, dec_W);
    packB_kernel<<<8192, 256>>>(Wih1, Whh1);
    init1_kernel<<<512, 256>>>(initp, ni_W1, ni_b1);
    init2_kernel<<<1024, 256>>>(ni_W2, ni_b2);
    init3_kernel<<<2048, 256>>>(ni_W3, ni_b3);
    xp_kernel<<<dim3(8, 2048), 256>>>(x);

    // sequential recurrence: 2 fused GEMM+cell kernels per step
    dim3 gridS(16, 8);  // 16 d-tiles x 8 b-tiles = 128 blocks
    const size_t HSZ = (size_t)BB * DD;
    for (int t = 0; t < FF; t++) {
        int p = t & 1;
        lstm_step<<<gridS, 256>>>(WA, h0 + (size_t)p * HSZ, h1 + (size_t)p * HSZ,
                                  Xp + (size_t)t * BB * G4, G4,
                                  c0, h0 + (size_t)(1 - p) * HSZ, nullptr, t);
        lstm_step<<<gridS, 256>>>(WB, h0 + (size_t)(1 - p) * HSZ, h1 + (size_t)p * HSZ,
                                  bias1v, 0,
                                  c1, h1 + (size_t)(1 - p) * HSZ, mc, t);
    }

    // final decode of preds for all (b,t)
    dec_kernel<<<16384, 256>>>(dec_W, dec_b, kp, mc);
}